// round 12
// baseline (speedup 1.0000x reference)
#include <cuda_runtime.h>
#include <math.h>
#include <float.h>
#include <stdint.h>

#define BB 64
#define NNT 197
#define CC 768
#define HH 12
#define HD 64
#define C3 2304
#define C4 3072
#define BNR (BB*NNT)   /* 12608 */

// ---------------- scratch (device globals; allocation is forbidden) ----------
__device__ float  g_xn  [(size_t)BNR*CC];
__device__ float  g_qkv [(size_t)BNR*C3];
__device__ float  g_attn[(size_t)BB*HH*NNT*NNT];
__device__ double g_attn0d[(size_t)BB*HH*NNT];  // fp64 row-0 attention per head
__device__ double g_vnormd[BNR];
__device__ float  g_pol [BNR];
__device__ int    g_srctok[BNR];   // token index 0..196 or -1
__device__ int    g_src   [BNR];   // global row into x, or -1
__device__ float  g_xo  [(size_t)BNR*CC];
__device__ float  g_x2  [(size_t)BNR*CC];
__device__ float  g_h1  [(size_t)BNR*C4];

// ---------------- LayerNorm: fp64 two-pass (matches jnp mean/var semantics) ---
__global__ __launch_bounds__(256) void lnd_kernel(
    const float* __restrict__ x, const float* __restrict__ g,
    const float* __restrict__ bta, const float* __restrict__ pol,
    float* __restrict__ out)
{
  __shared__ double sh[8];
  __shared__ double bc;
  const int row = blockIdx.x;
  const int tid = threadIdx.x;
  const float* xr = x + (size_t)row*CC;

  // pass 1: mean
  double s = 0.0;
  for (int c=tid;c<CC;c+=256) s += (double)xr[c];
#pragma unroll
  for (int o=16;o>0;o>>=1) s += __shfl_xor_sync(0xffffffffu, s, o);
  if ((tid&31)==0) sh[tid>>5] = s;
  __syncthreads();
  if (tid==0){ double a=0.0; for(int i=0;i<8;i++) a+=sh[i]; bc = a/(double)CC; }
  __syncthreads();
  const double mean = bc;
  __syncthreads();

  // pass 2: var = mean((x-mean)^2)
  double s2 = 0.0;
  for (int c=tid;c<CC;c+=256){ double d=(double)xr[c]-mean; s2 += d*d; }
#pragma unroll
  for (int o=16;o>0;o>>=1) s2 += __shfl_xor_sync(0xffffffffu, s2, o);
  if ((tid&31)==0) sh[tid>>5] = s2;
  __syncthreads();
  if (tid==0){ double a=0.0; for(int i=0;i<8;i++) a+=sh[i]; bc = a/(double)CC; }
  __syncthreads();
  const double var = bc;
  const double rs  = 1.0 / sqrt(var + 1e-5);
  const float  p   = pol ? pol[row] : 1.f;

  float* o = out + (size_t)row*CC;
  for (int c=tid;c<CC;c+=256)
    o[c] = (float)((((double)xr[c]-mean)*rs)*(double)g[c] + (double)bta[c]) * p;
}

// ---------------- 128x128x8 SGEMM, double-buffered smem -----------------------
// MODE 0: C = A@B
// MODE 1: C = (A@B + bias)*pol + gather(xraw, src)   (proj -> x2)
// MODE 2: C = gelu_exact(A@B + bias)                 (fc1)
// MODE 3: C = (A@B + bias + addm)*pol                (fc2 -> out)
template<int MODE>
__global__ __launch_bounds__(256) void sgemm128(
    const float* __restrict__ A, const float* __restrict__ B,
    const float* __restrict__ bias, float* __restrict__ C,
    int M, int N, int K,
    const float* __restrict__ xraw, const int* __restrict__ src,
    const float* __restrict__ pol, const float* __restrict__ addm)
{
  __shared__ float As[2][8][128];
  __shared__ float Bs[2][8][128];
  const int tid = threadIdx.x;
  const int bx = blockIdx.x, by = blockIdx.y;
  const int tx = tid & 15, ty = tid >> 4;
  const int arow = tid >> 1, acol = (tid & 1) << 2;
  const int brow = tid >> 5, bcol = (tid & 31) << 2;
  const int am = by*128 + arow;
  const bool aval = (am < M);
  const float* Ap = A + (size_t)am*K + acol;
  const float* Bp = B + (size_t)brow*N + bx*128 + bcol;
  float acc[8][8] = {};

  float4 av = aval ? *(const float4*)(Ap) : make_float4(0.f,0.f,0.f,0.f);
  float4 bv = *(const float4*)(Bp);
  As[0][acol+0][arow]=av.x; As[0][acol+1][arow]=av.y;
  As[0][acol+2][arow]=av.z; As[0][acol+3][arow]=av.w;
  *(float4*)&Bs[0][brow][bcol] = bv;
  __syncthreads();

  int buf = 0;
  for (int k0=0;k0<K;k0+=8){
    const bool more = (k0 + 8 < K);
    if (more){
      av = aval ? *(const float4*)(Ap + k0 + 8) : make_float4(0.f,0.f,0.f,0.f);
      bv = *(const float4*)(Bp + (size_t)(k0+8)*N);
    }
#pragma unroll
    for (int k=0;k<8;k++){
      float ar[8], br[8];
      *(float4*)&ar[0] = *(const float4*)&As[buf][k][ty*8];
      *(float4*)&ar[4] = *(const float4*)&As[buf][k][ty*8+4];
      *(float4*)&br[0] = *(const float4*)&Bs[buf][k][tx*8];
      *(float4*)&br[4] = *(const float4*)&Bs[buf][k][tx*8+4];
#pragma unroll
      for (int i=0;i<8;i++)
#pragma unroll
        for (int j=0;j<8;j++)
          acc[i][j] = fmaf(ar[i], br[j], acc[i][j]);
    }
    if (more){
      const int nb = buf ^ 1;
      As[nb][acol+0][arow]=av.x; As[nb][acol+1][arow]=av.y;
      As[nb][acol+2][arow]=av.z; As[nb][acol+3][arow]=av.w;
      *(float4*)&Bs[nb][brow][bcol] = bv;
      __syncthreads();
      buf = nb;
    }
  }

  const int cb = bx*128 + tx*8;
#pragma unroll
  for (int i=0;i<8;i++){
    const int r = by*128 + ty*8 + i;
    if (r >= M) continue;
    float p = 1.f; int s = 0;
    if (MODE==1 || MODE==3) p = pol[r];
    if (MODE==1) s = src[r];
    float* Crow = C + (size_t)r*N;
#pragma unroll
    for (int j=0;j<8;j++){
      const int c = cb + j;
      float v = acc[i][j];
      if (MODE==0){
        Crow[c] = v;
      } else if (MODE==1){
        float selx = (s >= 0) ? xraw[(size_t)s*CC + c] : 0.f;
        Crow[c] = (v + bias[c]) * p + selx;
      } else if (MODE==2){
        float t = v + bias[c];
        Crow[c] = 0.5f * t * (1.f + erff(t * 0.70710678118654752f));
      } else {
        Crow[c] = (v + bias[c] + addm[(size_t)r*N + c]) * p;
      }
    }
  }
}

// ---------------- S = (q @ k^T) * scale ---------------------------------------
__global__ __launch_bounds__(256) void qk_kernel(
    const float* __restrict__ qkv, float* __restrict__ attn)
{
  const int bh = blockIdx.z;
  const int b = bh/HH, h = bh%HH;
  const int n0 = blockIdx.y*64, m0 = blockIdx.x*64;
  __shared__ float As[16][64];
  __shared__ float Bs[16][64];
  const int tid=threadIdx.x, tx=tid&15, ty=tid>>4;
  const int lr=tid>>2, lc=(tid&3)<<2;
  const float* qb = qkv + (size_t)b*NNT*C3 + (size_t)h*HD;
  const float* kb = qb + CC;
  float acc[4][4] = {};
#pragma unroll
  for (int k0=0;k0<HD;k0+=16){
    float4 av = make_float4(0.f,0.f,0.f,0.f);
    float4 bv = make_float4(0.f,0.f,0.f,0.f);
    const int nq=n0+lr; if (nq<NNT) av = *(const float4*)(qb + (size_t)nq*C3 + k0 + lc);
    const int mk=m0+lr; if (mk<NNT) bv = *(const float4*)(kb + (size_t)mk*C3 + k0 + lc);
    As[lc+0][lr]=av.x; As[lc+1][lr]=av.y; As[lc+2][lr]=av.z; As[lc+3][lr]=av.w;
    Bs[lc+0][lr]=bv.x; Bs[lc+1][lr]=bv.y; Bs[lc+2][lr]=bv.z; Bs[lc+3][lr]=bv.w;
    __syncthreads();
#pragma unroll
    for (int k=0;k<16;k++){
      float4 a4 = *(const float4*)&As[k][ty<<2];
      float4 b4 = *(const float4*)&Bs[k][tx<<2];
      float ar[4]={a4.x,a4.y,a4.z,a4.w};
      float br[4]={b4.x,b4.y,b4.z,b4.w};
#pragma unroll
      for (int i=0;i<4;i++)
#pragma unroll
        for (int j=0;j<4;j++)
          acc[i][j] = fmaf(ar[i], br[j], acc[i][j]);
    }
    __syncthreads();
  }
  float* ob = attn + (size_t)bh*NNT*NNT;
#pragma unroll
  for (int i=0;i<4;i++){
    const int n = n0 + (ty<<2) + i;
    if (n >= NNT) continue;
#pragma unroll
    for (int j=0;j<4;j++){
      const int m = m0 + (tx<<2) + j;
      if (m < NNT) ob[(size_t)n*NNT + m] = acc[i][j] * 0.125f;
    }
  }
}

// ---------------- softmax_with_policy fp32 (full attn, output path) ----------
__global__ __launch_bounds__(256) void softmax_kernel(
    float* __restrict__ attn, const float* __restrict__ pol)
{
  const int row = blockIdx.x*8 + (threadIdx.x>>5);
  if (row >= BB*HH*NNT) return;
  const int lane = threadIdx.x & 31;
  const int n  = row % NNT;
  const int bh = row / NNT;
  const int b  = bh / HH;
  float* p = attn + (size_t)row*NNT;
  const float* pb = pol + b*NNT;
  float xv[7];
  float mx = -FLT_MAX;
#pragma unroll
  for (int it=0;it<7;it++){
    int m = lane + 32*it;
    xv[it] = (m<NNT) ? p[m] : -FLT_MAX;
    mx = fmaxf(mx, xv[it]);
  }
#pragma unroll
  for (int o=16;o>0;o>>=1) mx = fmaxf(mx, __shfl_xor_sync(0xffffffffu,mx,o));
  float av[7]; float sum=0.f;
#pragma unroll
  for (int it=0;it<7;it++){
    int m = lane + 32*it;
    if (m<NNT){
      float pm = pb[m];
      float ap = pm + (1.f-pm)*((m==n)?1.f:0.f);
      av[it] = expf(xv[it]-mx)*ap;
      sum += av[it];
    } else av[it]=0.f;
  }
#pragma unroll
  for (int o=16;o>0;o>>=1) sum += __shfl_xor_sync(0xffffffffu,sum,o);
  const float inv = 1.f/(sum + 1e-6f);
#pragma unroll
  for (int it=0;it<7;it++){
    int m = lane + 32*it;
    if (m<NNT) p[m] = (av[it] + (1e-6f/197.f)) * inv;
  }
}

// ---------------- fp64 row-0 attention per head (selection path) -------------
__global__ __launch_bounds__(256) void scorehead_kernel(
    const float* __restrict__ qkv, double* __restrict__ attn0d)
{
  const int bh = blockIdx.x;          // b*HH + h
  const int b = bh/HH, h = bh%HH;
  const int tid = threadIdx.x;
  __shared__ double q0s[HD];
  __shared__ double raws[NNT];
  __shared__ double red;
  if (tid < HD)
    q0s[tid] = (double)qkv[(size_t)(b*NNT)*C3 + h*HD + tid];
  __syncthreads();
  double rv = 0.0;
  if (tid < NNT){
    const float* kp = qkv + (size_t)(b*NNT+tid)*C3 + CC + h*HD;
    double s = 0.0;
    for (int d=0; d<HD; d++) s += q0s[d]*(double)kp[d];
    rv = s * 0.125;
    raws[tid] = rv;
  }
  __syncthreads();
  if (tid==0){
    double mx = raws[0];
    for (int m=1;m<NNT;m++) if (raws[m]>mx) mx=raws[m];
    red = mx;
  }
  __syncthreads();
  const double mx = red;
  double ev = 0.0;
  if (tid < NNT){ ev = exp(rv - mx); raws[tid] = ev; }
  __syncthreads();
  if (tid==0){
    double s=0.0; for (int m=0;m<NNT;m++) s += raws[m];
    red = s;
  }
  __syncthreads();
  const double sum = red;
  if (tid < NNT){
    const double epsN = (double)(1e-6f/197.0f);   // fp32 constant, as reference
    const double eps  = (double)1e-6f;
    attn0d[(size_t)bh*NNT + tid] = (ev + epsN)/(sum + eps);
  }
}

// ---------------- fp64 ||v|| per token (warp per row) -------------------------
__global__ __launch_bounds__(256) void vnormd_kernel(
    const float* __restrict__ qkv, double* __restrict__ vn)
{
  const int row = blockIdx.x*8 + (threadIdx.x>>5);
  if (row >= BNR) return;
  const int lane = threadIdx.x & 31;
  const float* p = qkv + (size_t)row*C3 + 2*CC;
  double s=0.0;
  for (int c=lane;c<CC;c+=32){ double v=(double)p[c]; s += v*v; }
#pragma unroll
  for (int o=16;o>0;o>>=1) s += __shfl_xor_sync(0xffffffffu,s,o);
  if (lane==0) vn[row] = sqrt(s);
}

// ---------------- token sampling, fp64 (one block per batch) ------------------
__device__ __forceinline__ void bitonic_int256(int* a, int tid){
  for (int k=2;k<=256;k<<=1)
    for (int j=k>>1;j>0;j>>=1){
      __syncthreads();
      int ixj = tid ^ j;
      if (ixj > tid){
        bool up = ((tid & k) == 0);
        int x=a[tid], y=a[ixj];
        if (up ? (x>y) : (x<y)){ a[tid]=y; a[ixj]=x; }
      }
    }
  __syncthreads();
}

__global__ __launch_bounds__(256) void sample_kernel(
    const double* __restrict__ attn0d, const double* __restrict__ vnormd,
    int* __restrict__ srctok, int* __restrict__ src, float* __restrict__ polr)
{
  const int b = blockIdx.x, tid = threadIdx.x;
  __shared__ double ss[256];
  __shared__ int    sidx[256];
  __shared__ double sncdf[200];
  __shared__ int    stok[256];
  __shared__ int    su[256];
  __shared__ double dred;

  // score (tokens 1..196) in fp64
  double sc = 0.0;
  if (tid < 196){
    const int m = tid + 1;
    double hs = 0.0;
    for (int h=0; h<HH; h++)
      hs += attn0d[((size_t)(b*HH+h))*NNT + m];
    sc = hs * vnormd[b*NNT + m];
  }
  ss[tid] = (tid<196) ? sc : 0.0;
  __syncthreads();
  if (tid==0){ double t=0.0; for (int j=0;j<196;j++) t += ss[j]; dred = t; }
  __syncthreads();
  const double total = dred;
  const double scn = sc / total;
  __syncthreads();

  ss[tid]   = (tid<196) ? scn : DBL_MAX;
  sidx[tid] = tid;
  __syncthreads();

  // ascending stable argsort (bitonic, index tie-break)
  for (int k=2;k<=256;k<<=1)
    for (int j=k>>1;j>0;j>>=1){
      __syncthreads();
      int ixj = tid ^ j;
      if (ixj > tid){
        bool up = ((tid & k) == 0);
        double a=ss[tid], bv=ss[ixj];
        int ia=sidx[tid], ib=sidx[ixj];
        bool aLb = (a<bv) || (a==bv && ia<ib);
        if (up ? !aLb : aLb){ ss[tid]=bv; ss[ixj]=a; sidx[tid]=ib; sidx[ixj]=ia; }
      }
    }
  __syncthreads();

  // sequential cumsum (fp64)
  if (tid==0){
    double r=0.0;
    for (int j=0;j<196;j++){ r += ss[j]; sncdf[j] = r; }
  }
  __syncthreads();
  // normalize cdf
  {
    double c0 = sncdf[0], c1 = sncdf[195];
    double rng = c1 - c0;
    double c  = (tid<196) ? sncdf[tid] : 0.0;
    __syncthreads();
    if (tid<196) sncdf[tid] = (c - c0) / rng;
  }
  __syncthreads();

  // ys_start = min(ncdf + (ncdf==0)*1e8)
  if (tid==0){
    double mn = DBL_MAX;
    for (int j=0;j<196;j++){
      double v = sncdf[j];
      double w = (v==0.0) ? v + 1e8 : v;
      if (w < mn) mn = w;
    }
    dred = mn;
  }
  __syncthreads();
  const double ys_start = dred;

  // tokens_to_pick: nearest ncdf (first argmin), fp64 with fp32 linspace grid
  if (tid < 196){
    float ysl32 = (tid==195) ? 1.0f
                 : __fmul_rn((float)tid, __fdiv_rn(1.0f, 195.0f));
    double t  = (double)ysl32 * 195.0;
    double u  = ys_start * (double)tid;
    double ys = ys_start + (t - u) / 195.0;
    double bd = fabs(ys - sncdf[0]); int bj = 0;
    for (int j=1;j<196;j++){
      double d = fabs(ys - sncdf[j]);
      if (d < bd){ bd = d; bj = j; }
    }
    stok[tid] = bj;
  } else stok[tid] = 0x7fffffff;
  __syncthreads();

  // get_unique_indices: sort, mark dups (and last-vs-1 quirk) as 196, sort
  bitonic_int256(stok, tid);
  int u = 0x7fffffff;
  if (tid < 196){
    int sv  = stok[tid];
    int nxt = (tid < 195) ? stok[tid+1] : 1;   // ones_like quirk in reference
    u = (nxt - sv == 0) ? 196 : sv;
  }
  __syncthreads();
  su[tid] = u;
  __syncthreads();
  bitonic_int256(su, tid);

  // emit per-output-row source token / source row / policy
  if (tid < NNT){
    int tok; float p;
    if (tid == 0){ tok = 0; p = 1.f; }
    else {
      int uu = su[tid-1];
      if (uu < 196){ tok = 1 + sidx[uu]; p = 1.f; }
      else         { tok = -1;           p = 0.f; }
    }
    srctok[b*NNT + tid] = tok;
    src   [b*NNT + tid] = (tok >= 0) ? (b*NNT + tok) : -1;
    polr  [b*NNT + tid] = p;
  }
}

// ---------------- xo = gathered_attn @ v --------------------------------------
__global__ __launch_bounds__(256) void av_kernel(
    const float* __restrict__ attn, const float* __restrict__ qkv,
    const int* __restrict__ srctok, float* __restrict__ xo)
{
  const int bh = blockIdx.y;
  const int b = bh/HH, h = bh%HH;
  const int i0 = blockIdx.x*64;
  __shared__ float As[16][64];
  __shared__ float Vs[16][64];
  __shared__ int stoks[64];
  const int tid=threadIdx.x, tx=tid&15, ty=tid>>4;
  if (tid < 64){
    int i = i0 + tid;
    stoks[tid] = (i < NNT) ? srctok[b*NNT + i] : -1;
  }
  __syncthreads();
  const float* ab = attn + (size_t)bh*NNT*NNT;
  const float* vb = qkv + 2*CC + (size_t)h*HD;
  float acc[4][4] = {};
  const int lr=tid>>2, lc=(tid&3)<<2;
  const int vk=tid>>4, vd=(tid&15)<<2;
  for (int m0=0;m0<NNT;m0+=16){
    const int s = stoks[lr];
#pragma unroll
    for (int t=0;t<4;t++){
      const int m = m0 + lc + t;
      As[lc+t][lr] = (s>=0 && m<NNT) ? ab[(size_t)s*NNT + m] : 0.f;
    }
    {
      const int m = m0 + vk;
      float4 v4 = make_float4(0.f,0.f,0.f,0.f);
      if (m < NNT) v4 = *(const float4*)(vb + (size_t)(b*NNT+m)*C3 + vd);
      *(float4*)&Vs[vk][vd] = v4;
    }
    __syncthreads();
#pragma unroll
    for (int k=0;k<16;k++){
      float4 a4 = *(const float4*)&As[k][ty<<2];
      float4 v4 = *(const float4*)&Vs[k][tx<<2];
      float ar[4]={a4.x,a4.y,a4.z,a4.w};
      float vr[4]={v4.x,v4.y,v4.z,v4.w};
#pragma unroll
      for (int i=0;i<4;i++)
#pragma unroll
        for (int j=0;j<4;j++)
          acc[i][j] = fmaf(ar[i], vr[j], acc[i][j]);
    }
    __syncthreads();
  }
#pragma unroll
  for (int i=0;i<4;i++){
    const int r = i0 + (ty<<2) + i;
    if (r >= NNT) continue;
#pragma unroll
    for (int j=0;j<4;j++)
      xo[((size_t)(b*NNT+r))*CC + h*HD + (tx<<2) + j] = acc[i][j];
  }
}

// ---------------- launch -------------------------------------------------------
extern "C" void kernel_launch(void* const* d_in, const int* in_sizes, int n_in,
                              void* d_out, int out_size)
{
  const float* x      = (const float*)d_in[0];
  const float* pol    = (const float*)d_in[1];
  const float* w_qkv  = (const float*)d_in[2];
  const float* w_proj = (const float*)d_in[3];
  const float* b_proj = (const float*)d_in[4];
  const float* g1     = (const float*)d_in[5];
  const float* b1     = (const float*)d_in[6];
  const float* g2     = (const float*)d_in[7];
  const float* b2     = (const float*)d_in[8];
  const float* w_fc1  = (const float*)d_in[9];
  const float* b_fc1  = (const float*)d_in[10];
  const float* w_fc2  = (const float*)d_in[11];
  const float* b_fc2  = (const float*)d_in[12];
  float* out = (float*)d_out;

  float *xn,*qkvb,*attn,*polr,*xo,*x2,*h1;
  double *attn0d,*vnormd;
  int *srctok,*src;
  cudaGetSymbolAddress((void**)&xn,      g_xn);
  cudaGetSymbolAddress((void**)&qkvb,    g_qkv);
  cudaGetSymbolAddress((void**)&attn,    g_attn);
  cudaGetSymbolAddress((void**)&attn0d,  g_attn0d);
  cudaGetSymbolAddress((void**)&vnormd,  g_vnormd);
  cudaGetSymbolAddress((void**)&polr,    g_pol);
  cudaGetSymbolAddress((void**)&srctok,  g_srctok);
  cudaGetSymbolAddress((void**)&src,     g_src);
  cudaGetSymbolAddress((void**)&xo,      g_xo);
  cudaGetSymbolAddress((void**)&x2,      g_x2);
  cudaGetSymbolAddress((void**)&h1,      g_h1);

  const int rowBlocks = (BNR + 127)/128;   // 99

  // 1) LN1 (fp64 two-pass, * policy folded for qkv)
  lnd_kernel<<<BNR,256>>>(x, g1, b1, pol, xn);
  // 2) qkv = xn @ w_qkv
  sgemm128<0><<<dim3(C3/128, rowBlocks),256>>>(xn, w_qkv, nullptr, qkvb,
      BNR, C3, CC, nullptr, nullptr, nullptr, nullptr);
  // 3) raw attention scores (fp32, output path)
  qk_kernel<<<dim3(4,4,BB*HH),256>>>(qkvb, attn);
  // 4) softmax with policy (fp32, in place)
  softmax_kernel<<<(BB*HH*NNT + 7)/8,256>>>(attn, pol);
  // 5) fp64 selection inputs: row-0 attention per head, ||v||
  scorehead_kernel<<<BB*HH,256>>>(qkvb, attn0d);
  vnormd_kernel<<<(BNR+7)/8,256>>>(qkvb, vnormd);
  // 6) adaptive token sampling (fp64)
  sample_kernel<<<BB,256>>>(attn0d, vnormd, srctok, src, polr);
  // 7) xo = gathered attn @ v
  av_kernel<<<dim3(4, BB*HH),256>>>(attn, qkvb, srctok, xo);
  // 8) x2 = (xo @ w_proj + b_proj)*pol + gather(x)
  sgemm128<1><<<dim3(CC/128, rowBlocks),256>>>(xo, w_proj, b_proj, x2,
      BNR, CC, CC, x, src, polr, nullptr);
  // 9) LN2
  lnd_kernel<<<BNR,256>>>(x2, g2, b2, nullptr, xn);
  // 10) fc1 + exact GELU
  sgemm128<2><<<dim3(C4/128, rowBlocks),256>>>(xn, w_fc1, b_fc1, h1,
      BNR, C4, CC, nullptr, nullptr, nullptr, nullptr);
  // 11) out = (fc2 + x2)*pol
  sgemm128<3><<<dim3(CC/128, rowBlocks),256>>>(h1, w_fc2, b_fc2, out,
      BNR, CC, C4, nullptr, nullptr, polr, x2);
}

// round 17
// speedup vs baseline: 1.6733x; 1.6733x over previous
#include <cuda_runtime.h>
#include <cuda_fp16.h>
#include <mma.h>
#include <math.h>
#include <float.h>
#include <stdint.h>

using namespace nvcuda;

#define BB 64
#define NNT 197
#define CC 768
#define HH 12
#define HD 64
#define C3 2304
#define C4 3072
#define BNR (BB*NNT)   /* 12608 */

// ---------------- scratch (device globals; allocation is forbidden) ----------
__device__ float  g_xn  [(size_t)BNR*CC];
__device__ float  g_qkv [(size_t)BNR*C3];
__device__ float  g_attn[(size_t)BB*HH*NNT*NNT];
__device__ double g_attn0d[(size_t)BB*HH*NNT];
__device__ double g_vnormd[BNR];
__device__ float  g_pol [BNR];
__device__ int    g_srctok[BNR];
__device__ int    g_src   [BNR];
__device__ float  g_xo  [(size_t)BNR*CC];
__device__ float  g_x2  [(size_t)BNR*CC];
__device__ float  g_h1  [(size_t)BNR*C4];
// fp16 scratch for HMMA GEMMs
__device__ half   g_ah [(size_t)BNR*C4];
__device__ half   g_wth[(size_t)CC*C4];

// ---------------- LayerNorm: fp64 two-pass ------------------------------------
__global__ __launch_bounds__(256) void lnd_kernel(
    const float* __restrict__ x, const float* __restrict__ g,
    const float* __restrict__ bta, const float* __restrict__ pol,
    float* __restrict__ out)
{
  __shared__ double sh[8];
  __shared__ double bc;
  const int row = blockIdx.x;
  const int tid = threadIdx.x;
  const float* xr = x + (size_t)row*CC;

  double s = 0.0;
  for (int c=tid;c<CC;c+=256) s += (double)xr[c];
#pragma unroll
  for (int o=16;o>0;o>>=1) s += __shfl_xor_sync(0xffffffffu, s, o);
  if ((tid&31)==0) sh[tid>>5] = s;
  __syncthreads();
  if (tid==0){ double a=0.0; for(int i=0;i<8;i++) a+=sh[i]; bc = a/(double)CC; }
  __syncthreads();
  const double mean = bc;
  __syncthreads();

  double s2 = 0.0;
  for (int c=tid;c<CC;c+=256){ double d=(double)xr[c]-mean; s2 += d*d; }
#pragma unroll
  for (int o=16;o>0;o>>=1) s2 += __shfl_xor_sync(0xffffffffu, s2, o);
  if ((tid&31)==0) sh[tid>>5] = s2;
  __syncthreads();
  if (tid==0){ double a=0.0; for(int i=0;i<8;i++) a+=sh[i]; bc = a/(double)CC; }
  __syncthreads();
  const double var = bc;
  const double rs  = 1.0 / sqrt(var + 1e-5);
  const float  p   = pol ? pol[row] : 1.f;

  float* o = out + (size_t)row*CC;
  for (int c=tid;c<CC;c+=256)
    o[c] = (float)((((double)xr[c]-mean)*rs)*(double)g[c] + (double)bta[c]) * p;
}

// ---------------- fp32 128x128x8 SGEMM (qkv only; feeds selection) ------------
__global__ __launch_bounds__(256) void sgemm0(
    const float* __restrict__ A, const float* __restrict__ B,
    float* __restrict__ C, int M, int N, int K)
{
  __shared__ float As[2][8][128];
  __shared__ float Bs[2][8][128];
  const int tid = threadIdx.x;
  const int bx = blockIdx.x, by = blockIdx.y;
  const int tx = tid & 15, ty = tid >> 4;
  const int arow = tid >> 1, acol = (tid & 1) << 2;
  const int brow = tid >> 5, bcol = (tid & 31) << 2;
  const int am = by*128 + arow;
  const bool aval = (am < M);
  const float* Ap = A + (size_t)am*K + acol;
  const float* Bp = B + (size_t)brow*N + bx*128 + bcol;
  float acc[8][8] = {};

  float4 av = aval ? *(const float4*)(Ap) : make_float4(0.f,0.f,0.f,0.f);
  float4 bv = *(const float4*)(Bp);
  As[0][acol+0][arow]=av.x; As[0][acol+1][arow]=av.y;
  As[0][acol+2][arow]=av.z; As[0][acol+3][arow]=av.w;
  *(float4*)&Bs[0][brow][bcol] = bv;
  __syncthreads();

  int buf = 0;
  for (int k0=0;k0<K;k0+=8){
    const bool more = (k0 + 8 < K);
    if (more){
      av = aval ? *(const float4*)(Ap + k0 + 8) : make_float4(0.f,0.f,0.f,0.f);
      bv = *(const float4*)(Bp + (size_t)(k0+8)*N);
    }
#pragma unroll
    for (int k=0;k<8;k++){
      float ar[8], br[8];
      *(float4*)&ar[0] = *(const float4*)&As[buf][k][ty*8];
      *(float4*)&ar[4] = *(const float4*)&As[buf][k][ty*8+4];
      *(float4*)&br[0] = *(const float4*)&Bs[buf][k][tx*8];
      *(float4*)&br[4] = *(const float4*)&Bs[buf][k][tx*8+4];
#pragma unroll
      for (int i=0;i<8;i++)
#pragma unroll
        for (int j=0;j<8;j++)
          acc[i][j] = fmaf(ar[i], br[j], acc[i][j]);
    }
    if (more){
      const int nb = buf ^ 1;
      As[nb][acol+0][arow]=av.x; As[nb][acol+1][arow]=av.y;
      As[nb][acol+2][arow]=av.z; As[nb][acol+3][arow]=av.w;
      *(float4*)&Bs[nb][brow][bcol] = bv;
      __syncthreads();
      buf = nb;
    }
  }
  const int cb = bx*128 + tx*8;
#pragma unroll
  for (int i=0;i<8;i++){
    const int r = by*128 + ty*8 + i;
    if (r >= M) continue;
    float* Crow = C + (size_t)r*N;
#pragma unroll
    for (int j=0;j<8;j++) Crow[cb+j] = acc[i][j];
  }
}

// ---------------- S = (q @ k^T) * scale ---------------------------------------
__global__ __launch_bounds__(256) void qk_kernel(
    const float* __restrict__ qkv, float* __restrict__ attn)
{
  const int bh = blockIdx.z;
  const int b = bh/HH, h = bh%HH;
  const int n0 = blockIdx.y*64, m0 = blockIdx.x*64;
  __shared__ float As[16][64];
  __shared__ float Bs[16][64];
  const int tid=threadIdx.x, tx=tid&15, ty=tid>>4;
  const int lr=tid>>2, lc=(tid&3)<<2;
  const float* qb = qkv + (size_t)b*NNT*C3 + (size_t)h*HD;
  const float* kb = qb + CC;
  float acc[4][4] = {};
#pragma unroll
  for (int k0=0;k0<HD;k0+=16){
    float4 av = make_float4(0.f,0.f,0.f,0.f);
    float4 bv = make_float4(0.f,0.f,0.f,0.f);
    const int nq=n0+lr; if (nq<NNT) av = *(const float4*)(qb + (size_t)nq*C3 + k0 + lc);
    const int mk=m0+lr; if (mk<NNT) bv = *(const float4*)(kb + (size_t)mk*C3 + k0 + lc);
    As[lc+0][lr]=av.x; As[lc+1][lr]=av.y; As[lc+2][lr]=av.z; As[lc+3][lr]=av.w;
    Bs[lc+0][lr]=bv.x; Bs[lc+1][lr]=bv.y; Bs[lc+2][lr]=bv.z; Bs[lc+3][lr]=bv.w;
    __syncthreads();
#pragma unroll
    for (int k=0;k<16;k++){
      float4 a4 = *(const float4*)&As[k][ty<<2];
      float4 b4 = *(const float4*)&Bs[k][tx<<2];
      float ar[4]={a4.x,a4.y,a4.z,a4.w};
      float br[4]={b4.x,b4.y,b4.z,b4.w};
#pragma unroll
      for (int i=0;i<4;i++)
#pragma unroll
        for (int j=0;j<4;j++)
          acc[i][j] = fmaf(ar[i], br[j], acc[i][j]);
    }
    __syncthreads();
  }
  float* ob = attn + (size_t)bh*NNT*NNT;
#pragma unroll
  for (int i=0;i<4;i++){
    const int n = n0 + (ty<<2) + i;
    if (n >= NNT) continue;
#pragma unroll
    for (int j=0;j<4;j++){
      const int m = m0 + (tx<<2) + j;
      if (m < NNT) ob[(size_t)n*NNT + m] = acc[i][j] * 0.125f;
    }
  }
}

// ---------------- softmax_with_policy fp32 ------------------------------------
__global__ __launch_bounds__(256) void softmax_kernel(
    float* __restrict__ attn, const float* __restrict__ pol)
{
  const int row = blockIdx.x*8 + (threadIdx.x>>5);
  if (row >= BB*HH*NNT) return;
  const int lane = threadIdx.x & 31;
  const int n  = row % NNT;
  const int bh = row / NNT;
  const int b  = bh / HH;
  float* p = attn + (size_t)row*NNT;
  const float* pb = pol + b*NNT;
  float xv[7];
  float mx = -FLT_MAX;
#pragma unroll
  for (int it=0;it<7;it++){
    int m = lane + 32*it;
    xv[it] = (m<NNT) ? p[m] : -FLT_MAX;
    mx = fmaxf(mx, xv[it]);
  }
#pragma unroll
  for (int o=16;o>0;o>>=1) mx = fmaxf(mx, __shfl_xor_sync(0xffffffffu,mx,o));
  float av[7]; float sum=0.f;
#pragma unroll
  for (int it=0;it<7;it++){
    int m = lane + 32*it;
    if (m<NNT){
      float pm = pb[m];
      float ap = pm + (1.f-pm)*((m==n)?1.f:0.f);
      av[it] = expf(xv[it]-mx)*ap;
      sum += av[it];
    } else av[it]=0.f;
  }
#pragma unroll
  for (int o=16;o>0;o>>=1) sum += __shfl_xor_sync(0xffffffffu,sum,o);
  const float inv = 1.f/(sum + 1e-6f);
#pragma unroll
  for (int it=0;it<7;it++){
    int m = lane + 32*it;
    if (m<NNT) p[m] = (av[it] + (1e-6f/197.f)) * inv;
  }
}

// ---------------- fp64 row-0 attention per head -------------------------------
__global__ __launch_bounds__(256) void scorehead_kernel(
    const float* __restrict__ qkv, double* __restrict__ attn0d)
{
  const int bh = blockIdx.x;
  const int b = bh/HH, h = bh%HH;
  const int tid = threadIdx.x;
  __shared__ double q0s[HD];
  __shared__ double raws[NNT];
  __shared__ double red;
  if (tid < HD)
    q0s[tid] = (double)qkv[(size_t)(b*NNT)*C3 + h*HD + tid];
  __syncthreads();
  double rv = 0.0;
  if (tid < NNT){
    const float* kp = qkv + (size_t)(b*NNT+tid)*C3 + CC + h*HD;
    double s = 0.0;
    for (int d=0; d<HD; d++) s += q0s[d]*(double)kp[d];
    rv = s * 0.125;
    raws[tid] = rv;
  }
  __syncthreads();
  if (tid==0){
    double mx = raws[0];
    for (int m=1;m<NNT;m++) if (raws[m]>mx) mx=raws[m];
    red = mx;
  }
  __syncthreads();
  const double mx = red;
  double ev = 0.0;
  if (tid < NNT){ ev = exp(rv - mx); raws[tid] = ev; }
  __syncthreads();
  if (tid==0){
    double s=0.0; for (int m=0;m<NNT;m++) s += raws[m];
    red = s;
  }
  __syncthreads();
  const double sum = red;
  if (tid < NNT){
    const double epsN = (double)(1e-6f/197.0f);
    const double eps  = (double)1e-6f;
    attn0d[(size_t)bh*NNT + tid] = (ev + epsN)/(sum + eps);
  }
}

// ---------------- fp64 ||v|| per token ----------------------------------------
__global__ __launch_bounds__(256) void vnormd_kernel(
    const float* __restrict__ qkv, double* __restrict__ vn)
{
  const int row = blockIdx.x*8 + (threadIdx.x>>5);
  if (row >= BNR) return;
  const int lane = threadIdx.x & 31;
  const float* p = qkv + (size_t)row*C3 + 2*CC;
  double s=0.0;
  for (int c=lane;c<CC;c+=32){ double v=(double)p[c]; s += v*v; }
#pragma unroll
  for (int o=16;o>0;o>>=1) s += __shfl_xor_sync(0xffffffffu,s,o);
  if (lane==0) vn[row] = sqrt(s);
}

// ---------------- token sampling, fp64 ----------------------------------------
__device__ __forceinline__ void bitonic_int256(int* a, int tid){
  for (int k=2;k<=256;k<<=1)
    for (int j=k>>1;j>0;j>>=1){
      __syncthreads();
      int ixj = tid ^ j;
      if (ixj > tid){
        bool up = ((tid & k) == 0);
        int x=a[tid], y=a[ixj];
        if (up ? (x>y) : (x<y)){ a[tid]=y; a[ixj]=x; }
      }
    }
  __syncthreads();
}

__global__ __launch_bounds__(256) void sample_kernel(
    const double* __restrict__ attn0d, const double* __restrict__ vnormd,
    int* __restrict__ srctok, int* __restrict__ src, float* __restrict__ polr)
{
  const int b = blockIdx.x, tid = threadIdx.x;
  __shared__ double ss[256];
  __shared__ int    sidx[256];
  __shared__ double sncdf[200];
  __shared__ int    stok[256];
  __shared__ int    su[256];
  __shared__ double dred;

  double sc = 0.0;
  if (tid < 196){
    const int m = tid + 1;
    double hs = 0.0;
    for (int h=0; h<HH; h++)
      hs += attn0d[((size_t)(b*HH+h))*NNT + m];
    sc = hs * vnormd[b*NNT + m];
  }
  ss[tid] = (tid<196) ? sc : 0.0;
  __syncthreads();
  if (tid==0){ double t=0.0; for (int j=0;j<196;j++) t += ss[j]; dred = t; }
  __syncthreads();
  const double total = dred;
  const double scn = sc / total;
  __syncthreads();

  ss[tid]   = (tid<196) ? scn : DBL_MAX;
  sidx[tid] = tid;
  __syncthreads();

  for (int k=2;k<=256;k<<=1)
    for (int j=k>>1;j>0;j>>=1){
      __syncthreads();
      int ixj = tid ^ j;
      if (ixj > tid){
        bool up = ((tid & k) == 0);
        double a=ss[tid], bv=ss[ixj];
        int ia=sidx[tid], ib=sidx[ixj];
        bool aLb = (a<bv) || (a==bv && ia<ib);
        if (up ? !aLb : aLb){ ss[tid]=bv; ss[ixj]=a; sidx[tid]=ib; sidx[ixj]=ia; }
      }
    }
  __syncthreads();

  if (tid==0){
    double r=0.0;
    for (int j=0;j<196;j++){ r += ss[j]; sncdf[j] = r; }
  }
  __syncthreads();
  {
    double c0 = sncdf[0], c1 = sncdf[195];
    double rng = c1 - c0;
    double c  = (tid<196) ? sncdf[tid] : 0.0;
    __syncthreads();
    if (tid<196) sncdf[tid] = (c - c0) / rng;
  }
  __syncthreads();

  if (tid==0){
    double mn = DBL_MAX;
    for (int j=0;j<196;j++){
      double v = sncdf[j];
      double w = (v==0.0) ? v + 1e8 : v;
      if (w < mn) mn = w;
    }
    dred = mn;
  }
  __syncthreads();
  const double ys_start = dred;

  if (tid < 196){
    float ysl32 = (tid==195) ? 1.0f
                 : __fmul_rn((float)tid, __fdiv_rn(1.0f, 195.0f));
    double t  = (double)ysl32 * 195.0;
    double u  = ys_start * (double)tid;
    double ys = ys_start + (t - u) / 195.0;
    double bd = fabs(ys - sncdf[0]); int bj = 0;
    for (int j=1;j<196;j++){
      double d = fabs(ys - sncdf[j]);
      if (d < bd){ bd = d; bj = j; }
    }
    stok[tid] = bj;
  } else stok[tid] = 0x7fffffff;
  __syncthreads();

  bitonic_int256(stok, tid);
  int u = 0x7fffffff;
  if (tid < 196){
    int sv  = stok[tid];
    int nxt = (tid < 195) ? stok[tid+1] : 1;
    u = (nxt - sv == 0) ? 196 : sv;
  }
  __syncthreads();
  su[tid] = u;
  __syncthreads();
  bitonic_int256(su, tid);

  if (tid < NNT){
    int tok; float p;
    if (tid == 0){ tok = 0; p = 1.f; }
    else {
      int uu = su[tid-1];
      if (uu < 196){ tok = 1 + sidx[uu]; p = 1.f; }
      else         { tok = -1;           p = 0.f; }
    }
    srctok[b*NNT + tid] = tok;
    src   [b*NNT + tid] = (tok >= 0) ? (b*NNT + tok) : -1;
    polr  [b*NNT + tid] = p;
  }
}

// ---------------- xo = gathered_attn @ v --------------------------------------
__global__ __launch_bounds__(256) void av_kernel(
    const float* __restrict__ attn, const float* __restrict__ qkv,
    const int* __restrict__ srctok, float* __restrict__ xo)
{
  const int bh = blockIdx.y;
  const int b = bh/HH, h = bh%HH;
  const int i0 = blockIdx.x*64;
  __shared__ float As[16][64];
  __shared__ float Vs[16][64];
  __shared__ int stoks[64];
  const int tid=threadIdx.x, tx=tid&15, ty=tid>>4;
  if (tid < 64){
    int i = i0 + tid;
    stoks[tid] = (i < NNT) ? srctok[b*NNT + i] : -1;
  }
  __syncthreads();
  const float* ab = attn + (size_t)bh*NNT*NNT;
  const float* vb = qkv + 2*CC + (size_t)h*HD;
  float acc[4][4] = {};
  const int lr=tid>>2, lc=(tid&3)<<2;
  const int vk=tid>>4, vd=(tid&15)<<2;
  for (int m0=0;m0<NNT;m0+=16){
    const int s = stoks[lr];
#pragma unroll
    for (int t=0;t<4;t++){
      const int m = m0 + lc + t;
      As[lc+t][lr] = (s>=0 && m<NNT) ? ab[(size_t)s*NNT + m] : 0.f;
    }
    {
      const int m = m0 + vk;
      float4 v4 = make_float4(0.f,0.f,0.f,0.f);
      if (m < NNT) v4 = *(const float4*)(vb + (size_t)(b*NNT+m)*C3 + vd);
      *(float4*)&Vs[vk][vd] = v4;
    }
    __syncthreads();
#pragma unroll
    for (int k=0;k<16;k++){
      float4 a4 = *(const float4*)&As[k][ty<<2];
      float4 v4 = *(const float4*)&Vs[k][tx<<2];
      float ar[4]={a4.x,a4.y,a4.z,a4.w};
      float vr[4]={v4.x,v4.y,v4.z,v4.w};
#pragma unroll
      for (int i=0;i<4;i++)
#pragma unroll
        for (int j=0;j<4;j++)
          acc[i][j] = fmaf(ar[i], vr[j], acc[i][j]);
    }
    __syncthreads();
  }
#pragma unroll
  for (int i=0;i<4;i++){
    const int r = i0 + (ty<<2) + i;
    if (r >= NNT) continue;
#pragma unroll
    for (int j=0;j<4;j++)
      xo[((size_t)(b*NNT+r))*CC + h*HD + (tx<<2) + j] = acc[i][j];
  }
}

// ================= fp16 WMMA GEMM path (proj / fc1 / fc2) =====================
__global__ __launch_bounds__(256) void aconvh_kernel(
    const float* __restrict__ a, half* __restrict__ h, int n)
{
  int i = blockIdx.x*256 + threadIdx.x;
  if (i < n) h[i] = __float2half(a[i]);
}

// weight [K][N] fp32 -> transposed [N][K] fp16
__global__ __launch_bounds__(256) void wconvh_kernel(
    const float* __restrict__ w, half* __restrict__ wt, int K, int N)
{
  __shared__ float t[32][33];
  const int kb = blockIdx.y*32, nb = blockIdx.x*32;
  const int tx = threadIdx.x & 31, ty = threadIdx.x >> 5;
  for (int i = ty; i < 32; i += 8)
    t[i][tx] = w[(size_t)(kb+i)*N + nb + tx];
  __syncthreads();
  for (int i = ty; i < 32; i += 8)
    wt[(size_t)(nb+i)*K + kb + tx] = __float2half(t[tx][i]);
}

// MODE 1: C=(A@B + bias)*pol + gather(xraw,src)    (proj)
// MODE 2: C=gelu(A@B + bias)                       (fc1)
// MODE 3: C=(A@B + bias + addm)*pol                (fc2)
template<int MODE>
__global__ __launch_bounds__(256) void hgemm(
    const half* __restrict__ A, const half* __restrict__ Bt,
    const float* __restrict__ bias, float* __restrict__ C,
    int M, int N, int K,
    const float* __restrict__ xraw, const int* __restrict__ src,
    const float* __restrict__ pol, const float* __restrict__ addm)
{
  __shared__ __align__(16) unsigned char sbuf[40960];
  half (*As)[40] = reinterpret_cast<half(*)[40]>(sbuf);            // [2*128][40]
  half (*Bs)[40] = reinterpret_cast<half(*)[40]>(sbuf + 20480);    // [2*128][40]
  const int tid = threadIdx.x, wid = tid>>5, lane = tid&31;
  const int m0 = blockIdx.y*128, n0 = blockIdx.x*128;
  const int wm = wid & 1, wn = wid >> 1;   // 2 x 4 warps; warp tile 64 x 32

  wmma::fragment<wmma::accumulator,16,16,16,float> cf[4][2];
#pragma unroll
  for (int i=0;i<4;i++)
#pragma unroll
    for (int j=0;j<2;j++) wmma::fill_fragment(cf[i][j], 0.f);

  // chunk loaders: 128x32 halves = 4096 = 256 thr * 2 * 8
  const int la_r0 = (tid*8) >> 5,        la_c = (tid*8) & 31;
  const int la_r1 = ((2048+tid*8) >> 5);
  uint4 pa0, pa1, pb0, pb1;

  // prologue: chunk 0 -> buf 0
  {
    uint4 a0 = (m0+la_r0 < M) ? *(const uint4*)(A + (size_t)(m0+la_r0)*K + la_c) : make_uint4(0,0,0,0);
    uint4 a1 = (m0+la_r1 < M) ? *(const uint4*)(A + (size_t)(m0+la_r1)*K + la_c) : make_uint4(0,0,0,0);
    uint4 b0 = *(const uint4*)(Bt + (size_t)(n0+la_r0)*K + la_c);
    uint4 b1 = *(const uint4*)(Bt + (size_t)(n0+la_r1)*K + la_c);
    *(uint4*)&As[la_r0][la_c] = a0;  *(uint4*)&As[la_r1][la_c] = a1;
    *(uint4*)&Bs[la_r0][la_c] = b0;  *(uint4*)&Bs[la_r1][la_c] = b1;
  }
  __syncthreads();

  int buf = 0;
  for (int k0=0;k0<K;k0+=32){
    const bool more = (k0 + 32 < K);
    if (more){
      const int kn = k0 + 32;
      pa0 = (m0+la_r0 < M) ? *(const uint4*)(A + (size_t)(m0+la_r0)*K + kn + la_c) : make_uint4(0,0,0,0);
      pa1 = (m0+la_r1 < M) ? *(const uint4*)(A + (size_t)(m0+la_r1)*K + kn + la_c) : make_uint4(0,0,0,0);
      pb0 = *(const uint4*)(Bt + (size_t)(n0+la_r0)*K + kn + la_c);
      pb1 = *(const uint4*)(Bt + (size_t)(n0+la_r1)*K + kn + la_c);
    }
#pragma unroll
    for (int ks=0; ks<2; ks++){
      wmma::fragment<wmma::matrix_a,16,16,16,half,wmma::row_major> af[4];
      wmma::fragment<wmma::matrix_b,16,16,16,half,wmma::col_major> bf[2];
#pragma unroll
      for (int i=0;i<4;i++)
        wmma::load_matrix_sync(af[i], &As[buf*128 + wm*64 + i*16][ks*16], 40);
#pragma unroll
      for (int j=0;j<2;j++)
        wmma::load_matrix_sync(bf[j], &Bs[buf*128 + wn*32 + j*16][ks*16], 40);
#pragma unroll
      for (int i=0;i<4;i++)
#pragma unroll
        for (int j=0;j<2;j++)
          wmma::mma_sync(cf[i][j], af[i], bf[j], cf[i][j]);
    }
    if (more){
      const int nb = buf ^ 1;
      *(uint4*)&As[nb*128+la_r0][la_c] = pa0;  *(uint4*)&As[nb*128+la_r1][la_c] = pa1;
      *(uint4*)&Bs[nb*128+la_r0][la_c] = pb0;  *(uint4*)&Bs[nb*128+la_r1][la_c] = pb1;
      __syncthreads();
      buf = nb;
    }
  }
  __syncthreads();   // before reusing sbuf as epilogue staging

  // per-warp staging: 16 x 20 floats (ldm 20 = 80 B, WMMA-legal) = 1280 B
  float* cs = (float*)(sbuf + wid*1280);
  const int er  = lane & 15;
  const int ec0 = (lane >> 4) * 8;
#pragma unroll
  for (int i=0;i<4;i++){
    const int mrow = m0 + wm*64 + i*16;
    if (mrow >= M) continue;               // M % 64 == 0 vs 128-tile -> halves fully valid/invalid
#pragma unroll
    for (int j=0;j<2;j++){
      wmma::store_matrix_sync(cs, cf[i][j], 20, wmma::mem_row_major);
      __syncwarp();
      const int grow = mrow + er;
      float p = 1.f; int s = 0; const float* addrow = nullptr;
      if (MODE==1 || MODE==3) p = pol[grow];
      if (MODE==1) s = src[grow];
      if (MODE==3) addrow = addm + (size_t)grow*N;
      float* Crow = C + (size_t)grow*N;
      const int cb = n0 + wn*32 + j*16 + ec0;
#pragma unroll
      for (int q=0;q<8;q++){
        const int c = cb + q;
        float v = cs[er*20 + ec0 + q];
        if (MODE==1){
          float selx = (s >= 0) ? xraw[(size_t)s*CC + c] : 0.f;
          Crow[c] = (v + bias[c]) * p + selx;
        } else if (MODE==2){
          float t = v + bias[c];
          Crow[c] = 0.5f * t * (1.f + erff(t * 0.70710678118654752f));
        } else {
          Crow[c] = (v + bias[c] + addrow[c]) * p;
        }
      }
      __syncwarp();
    }
  }
}

// ---------------- launch -------------------------------------------------------
extern "C" void kernel_launch(void* const* d_in, const int* in_sizes, int n_in,
                              void* d_out, int out_size)
{
  const float* x      = (const float*)d_in[0];
  const float* pol    = (const float*)d_in[1];
  const float* w_qkv  = (const float*)d_in[2];
  const float* w_proj = (const float*)d_in[3];
  const float* b_proj = (const float*)d_in[4];
  const float* g1     = (const float*)d_in[5];
  const float* b1     = (const float*)d_in[6];
  const float* g2     = (const float*)d_in[7];
  const float* b2     = (const float*)d_in[8];
  const float* w_fc1  = (const float*)d_in[9];
  const float* b_fc1  = (const float*)d_in[10];
  const float* w_fc2  = (const float*)d_in[11];
  const float* b_fc2  = (const float*)d_in[12];
  float* out = (float*)d_out;

  float *xn,*qkvb,*attn,*polr,*xo,*x2,*h1;
  double *attn0d,*vnormd;
  int *srctok,*src;
  half *ah,*wth;
  cudaGetSymbolAddress((void**)&xn,      g_xn);
  cudaGetSymbolAddress((void**)&qkvb,    g_qkv);
  cudaGetSymbolAddress((void**)&attn,    g_attn);
  cudaGetSymbolAddress((void**)&attn0d,  g_attn0d);
  cudaGetSymbolAddress((void**)&vnormd,  g_vnormd);
  cudaGetSymbolAddress((void**)&polr,    g_pol);
  cudaGetSymbolAddress((void**)&srctok,  g_srctok);
  cudaGetSymbolAddress((void**)&src,     g_src);
  cudaGetSymbolAddress((void**)&xo,      g_xo);
  cudaGetSymbolAddress((void**)&x2,      g_x2);
  cudaGetSymbolAddress((void**)&h1,      g_h1);
  cudaGetSymbolAddress((void**)&ah,      g_ah);
  cudaGetSymbolAddress((void**)&wth,     g_wth);

  const int rowBlocks = (BNR + 127)/128;   // 99

  // 1) LN1 (fp64 two-pass, * policy)
  lnd_kernel<<<BNR,256>>>(x, g1, b1, pol, xn);
  // 2) qkv (fp32 exact — feeds selection)
  sgemm0<<<dim3(C3/128, rowBlocks),256>>>(xn, w_qkv, qkvb, BNR, C3, CC);
  // 3-4) attention scores + softmax
  qk_kernel<<<dim3(4,4,BB*HH),256>>>(qkvb, attn);
  softmax_kernel<<<(BB*HH*NNT + 7)/8,256>>>(attn, pol);
  // 5-6) fp64 selection
  scorehead_kernel<<<BB*HH,256>>>(qkvb, attn0d);
  vnormd_kernel<<<(BNR+7)/8,256>>>(qkvb, vnormd);
  sample_kernel<<<BB,256>>>(attn0d, vnormd, srctok, src, polr);
  // 7) xo = gathered attn @ v
  av_kernel<<<dim3(4, BB*HH),256>>>(attn, qkvb, srctok, xo);
  // 8) proj (HMMA fp16): x2 = (xo@Wp + b)*pol + gather(x)
  aconvh_kernel<<<(BNR*CC+255)/256,256>>>(xo, ah, BNR*CC);
  wconvh_kernel<<<dim3(CC/32, CC/32), 256>>>(w_proj, wth, CC, CC);
  hgemm<1><<<dim3(CC/128, rowBlocks),256>>>(ah, wth, b_proj, x2,
      BNR, CC, CC, x, src, polr, nullptr);
  // 9) LN2
  lnd_kernel<<<BNR,256>>>(x2, g2, b2, nullptr, xn);
  // 10) fc1 + GELU (HMMA fp16)
  aconvh_kernel<<<(BNR*CC+255)/256,256>>>(xn, ah, BNR*CC);
  wconvh_kernel<<<dim3(C4/32, CC/32), 256>>>(w_fc1, wth, CC, C4);
  hgemm<2><<<dim3(C4/128, rowBlocks),256>>>(ah, wth, b_fc1, h1,
      BNR, C4, CC, nullptr, nullptr, nullptr, nullptr);
  // 11) fc2 + residual (HMMA fp16)
  aconvh_kernel<<<(BNR*C4+255)/256,256>>>(h1, ah, BNR*C4);
  wconvh_kernel<<<dim3(CC/32, C4/32), 256>>>(w_fc2, wth, C4, CC);
  hgemm<3><<<dim3(CC/128, rowBlocks),256>>>(ah, wth, b_fc2, out,
      BNR, CC, C4, nullptr, nullptr, polr, x2);
}